// round 5
// baseline (speedup 1.0000x reference)
#include <cuda_runtime.h>
#include <cstdint>
#include <math.h>

// Problem constants: B=2, S=2048, D=1024, H=16, hd=64
#define SEQ   2048
#define DMODEL 1024
#define NH    16
#define HD    64
#define MTOT  4096   // B*S

// ---------------- scratch (no cudaMalloc allowed) ----------------
// All three hold tf32-rounded bits (converted in qkv_gemm epilogue).
// g_K additionally stores each 8-dim group pair-permuted:
//   within group: pos = ((d&3)<<1) | ((d&7)>>2)  so (d, d+4) are adjacent.
__device__ float g_Q[MTOT * DMODEL];
__device__ float g_K[MTOT * DMODEL];
__device__ float g_V[MTOT * DMODEL];

// ---------------- helpers ----------------
__device__ __forceinline__ uint32_t f2tf(float x) {
    uint32_t u;
    asm("cvt.rna.tf32.f32 %0, %1;" : "=r"(u) : "f"(x));
    return u;
}

__device__ __forceinline__ void mma8(float* c, const uint32_t* a, uint32_t b0, uint32_t b1) {
    asm volatile(
        "mma.sync.aligned.m16n8k8.row.col.f32.tf32.tf32.f32 "
        "{%0,%1,%2,%3}, {%4,%5,%6,%7}, {%8,%9}, {%0,%1,%2,%3};"
        : "+f"(c[0]), "+f"(c[1]), "+f"(c[2]), "+f"(c[3])
        : "r"(a[0]), "r"(a[1]), "r"(a[2]), "r"(a[3]), "r"(b0), "r"(b1));
}

__device__ __forceinline__ uint32_t smem_u32(const void* p) {
    return (uint32_t)__cvta_generic_to_shared(p);
}
__device__ __forceinline__ void cpa16(uint32_t dst, const void* src) {
    asm volatile("cp.async.ca.shared.global [%0], [%1], 16;" :: "r"(dst), "l"(src));
}

// ======================================================================
// Kernel 1: QKV projection GEMM.
// Epilogue writes tf32-rounded values; K is pair-permuted per 8-group.
// ======================================================================
__global__ __launch_bounds__(256) void qkv_gemm(
    const float* __restrict__ x,
    const float* __restrict__ Wq, const float* __restrict__ Wk, const float* __restrict__ Wv,
    const float* __restrict__ bq, const float* __restrict__ bk, const float* __restrict__ bv)
{
    __shared__ float As[128][36];   // frag bank (4g+t)%32, conflict-free
    __shared__ float Bs[32][136];   // frag bank (8t+g)%32, conflict-free

    const float* W; const float* bias; float* outp;
    if (blockIdx.z == 0)      { W = Wq; bias = bq; outp = g_Q; }
    else if (blockIdx.z == 1) { W = Wk; bias = bk; outp = g_K; }
    else                      { W = Wv; bias = bv; outp = g_V; }

    const int tid  = threadIdx.x;
    const int warp = tid >> 5, lane = tid & 31;
    const int g = lane >> 2, t = lane & 3;
    const int wr = warp >> 1;          // 0..3 (m)
    const int wc = warp & 1;           // 0..1 (n)
    const int m0 = blockIdx.y * 128;
    const int n0 = blockIdx.x * 128;

    float acc[2][8][4] = {};

    for (int k0 = 0; k0 < DMODEL; k0 += 32) {
        #pragma unroll
        for (int r = 0; r < 4; r++) {
            int i = tid + 256 * r;           // 0..1023
            int row = i >> 3;
            int c4  = (i & 7) << 2;
            float4 v = *(const float4*)&x[(m0 + row) * DMODEL + k0 + c4];
            As[row][c4 + 0] = __uint_as_float(f2tf(v.x));
            As[row][c4 + 1] = __uint_as_float(f2tf(v.y));
            As[row][c4 + 2] = __uint_as_float(f2tf(v.z));
            As[row][c4 + 3] = __uint_as_float(f2tf(v.w));
        }
        #pragma unroll
        for (int r = 0; r < 4; r++) {
            int i = tid + 256 * r;
            int row = i >> 5;
            int c4  = (i & 31) << 2;
            float4 v = *(const float4*)&W[(k0 + row) * DMODEL + n0 + c4];
            Bs[row][c4 + 0] = __uint_as_float(f2tf(v.x));
            Bs[row][c4 + 1] = __uint_as_float(f2tf(v.y));
            Bs[row][c4 + 2] = __uint_as_float(f2tf(v.z));
            Bs[row][c4 + 3] = __uint_as_float(f2tf(v.w));
        }
        __syncthreads();

        #pragma unroll
        for (int ks = 0; ks < 4; ks++) {
            const int kk = ks * 8;
            uint32_t a[2][4], bb[8][2];
            #pragma unroll
            for (int mt = 0; mt < 2; mt++) {
                int rb = wr * 32 + mt * 16;
                a[mt][0] = __float_as_uint(As[rb + g    ][kk + t    ]);
                a[mt][1] = __float_as_uint(As[rb + g + 8][kk + t    ]);
                a[mt][2] = __float_as_uint(As[rb + g    ][kk + t + 4]);
                a[mt][3] = __float_as_uint(As[rb + g + 8][kk + t + 4]);
            }
            #pragma unroll
            for (int nt = 0; nt < 8; nt++) {
                int cb = wc * 64 + nt * 8;
                bb[nt][0] = __float_as_uint(Bs[kk + t    ][cb + g]);
                bb[nt][1] = __float_as_uint(Bs[kk + t + 4][cb + g]);
            }
            #pragma unroll
            for (int mt = 0; mt < 2; mt++)
                #pragma unroll
                for (int nt = 0; nt < 8; nt++)
                    mma8(acc[mt][nt], a[mt], bb[nt][0], bb[nt][1]);
        }
        __syncthreads();
    }

    // epilogue: + bias, convert to tf32 bits, write.
    const bool isK = (blockIdx.z == 1);
    #pragma unroll
    for (int mt = 0; mt < 2; mt++) {
        int row = m0 + wr * 32 + mt * 16 + g;
        #pragma unroll
        for (int nt = 0; nt < 8; nt++) {
            int col = n0 + wc * 64 + nt * 8 + 2 * t;
            float b0v = bias[col], b1v = bias[col + 1];
            float e00 = __uint_as_float(f2tf(acc[mt][nt][0] + b0v));
            float e01 = __uint_as_float(f2tf(acc[mt][nt][1] + b1v));
            float e10 = __uint_as_float(f2tf(acc[mt][nt][2] + b0v));
            float e11 = __uint_as_float(f2tf(acc[mt][nt][3] + b1v));
            if (isK) {
                // pair-permute within the 8-group: w -> ((w&3)<<1) | (w>>2)
                int wbase = col & ~7;
                int p0 = wbase + (((2 * t)     & 3) << 1) + (t >> 1);
                int p1 = wbase + (((2 * t + 1) & 3) << 1) + (t >> 1);
                outp[(size_t)row       * DMODEL + p0] = e00;
                outp[(size_t)row       * DMODEL + p1] = e01;
                outp[(size_t)(row + 8) * DMODEL + p0] = e10;
                outp[(size_t)(row + 8) * DMODEL + p1] = e11;
            } else {
                *(float2*)&outp[(size_t)row       * DMODEL + col] = make_float2(e00, e01);
                *(float2*)&outp[(size_t)(row + 8) * DMODEL + col] = make_float2(e10, e11);
            }
        }
    }
}

// ======================================================================
// Kernel 2: flash attention v4 (R1 shape + CORRECT cp.async pipeline).
// grid = (SEQ/64, B*NH), 128 threads (4 warps), warp owns 16 q-rows.
// Pipeline invariant: before computing tile t, exactly group t has
// completed; wait_group constant equals pending-group count (1 mid-loop,
// 0 at tail).
// ======================================================================
#define KVT     32
#define NTILES  (SEQ / KVT)      // 64
#define KS_STRIDE 72
#define PS_STRIDE 40

__global__ __launch_bounds__(128) void attn_kernel(float* __restrict__ out)
{
    __shared__ float Ks[2][KVT][KS_STRIDE];   // paired-d layout (as stored in g_K)
    __shared__ float Vs[2][KVT][KS_STRIDE];   // plain [key][d]
    __shared__ float Ps[64][PS_STRIDE];       // paired-col P, 16 rows per warp

    const int tid = threadIdx.x, warp = tid >> 5, lane = tid & 31;
    const int g = lane >> 2, t = lane & 3;
    const int bh = blockIdx.y;
    const int b  = bh >> 4;
    const int h  = bh & 15;
    const int q0 = blockIdx.x * 64;

    const float* Kbase = g_K + (size_t)(b * SEQ) * DMODEL + h * HD;
    const float* Vbase = g_V + (size_t)(b * SEQ) * DMODEL + h * HD;

    // fill roles: thread -> (key row, 64B chunk)
    const int frow = tid >> 2;              // 0..31
    const int fc   = (tid & 3) * 16;        // float offset: 0,16,32,48
    const uint32_t sK0 = smem_u32(&Ks[0][frow][fc]);
    const uint32_t sV0 = smem_u32(&Vs[0][frow][fc]);
    const uint32_t stageBytes = (uint32_t)(KVT * KS_STRIDE * 4);

    // issue cp.async for one stage (8 x 16B per thread), one commit group
    auto issue = [&](int stage, int kv0) {
        const float* kp = Kbase + (size_t)(kv0 + frow) * DMODEL + fc;
        const float* vp = Vbase + (size_t)(kv0 + frow) * DMODEL + fc;
        uint32_t dk = sK0 + stage * stageBytes;
        uint32_t dv = sV0 + stage * stageBytes;
        #pragma unroll
        for (int i = 0; i < 4; i++) cpa16(dk + i * 16, kp + i * 4);
        #pragma unroll
        for (int i = 0; i < 4; i++) cpa16(dv + i * 16, vp + i * 4);
        asm volatile("cp.async.commit_group;" ::: "memory");
    };

    issue(0, 0);   // 1 group pending

    // --- Q fragments (already tf32 bits in g_Q) ---
    const int qrow = b * SEQ + q0 + warp * 16;
    uint32_t qa[8][4];
    #pragma unroll
    for (int kt = 0; kt < 8; kt++) {
        qa[kt][0] = __float_as_uint(g_Q[(size_t)(qrow + g    ) * DMODEL + h * HD + kt * 8 + t    ]);
        qa[kt][1] = __float_as_uint(g_Q[(size_t)(qrow + g + 8) * DMODEL + h * HD + kt * 8 + t    ]);
        qa[kt][2] = __float_as_uint(g_Q[(size_t)(qrow + g    ) * DMODEL + h * HD + kt * 8 + t + 4]);
        qa[kt][3] = __float_as_uint(g_Q[(size_t)(qrow + g + 8) * DMODEL + h * HD + kt * 8 + t + 4]);
    }

    float m2[2]  = {-INFINITY, -INFINITY};
    float ls[2]  = {0.f, 0.f};
    float o[8][4] = {};

    const float SC = 0.125f * 1.44269504088896f;  // 1/sqrt(64) * log2(e)

    // paired-column P store positions
    const int pkA = (((2 * t)     & 3) << 1) + (t >> 1);   // col 2t
    const int pkB = (((2 * t + 1) & 3) << 1) + (t >> 1);   // col 2t+1
    const int rg = warp * 16 + g;

    for (int tile = 0; tile < NTILES; tile++) {
        const int stage = tile & 1;

        if (tile + 1 < NTILES) {
            issue(stage ^ 1, (tile + 1) * KVT);               // 2 pending
            asm volatile("cp.async.wait_group 1;" ::: "memory");  // group 'tile' done
        } else {
            asm volatile("cp.async.wait_group 0;" ::: "memory");  // drain all
        }
        __syncthreads();   // make stage's smem visible to all threads

        // --- S = Q @ K^T : b-frags as LDS.64 from paired K ---
        float s[4][4] = {};
        #pragma unroll
        for (int nt = 0; nt < 4; nt++) {
            #pragma unroll
            for (int kt = 0; kt < 8; kt++) {
                float2 bb = *(const float2*)&Ks[stage][nt * 8 + g][kt * 8 + 2 * t];
                mma8(s[nt], qa[kt], __float_as_uint(bb.x), __float_as_uint(bb.y));
            }
        }

        // --- log2-domain scale + tile row max ---
        float mx0 = -INFINITY, mx1 = -INFINITY;
        #pragma unroll
        for (int nt = 0; nt < 4; nt++) {
            s[nt][0] *= SC; s[nt][1] *= SC; s[nt][2] *= SC; s[nt][3] *= SC;
            mx0 = fmaxf(mx0, fmaxf(s[nt][0], s[nt][1]));
            mx1 = fmaxf(mx1, fmaxf(s[nt][2], s[nt][3]));
        }
        mx0 = fmaxf(mx0, __shfl_xor_sync(0xffffffffu, mx0, 1));
        mx0 = fmaxf(mx0, __shfl_xor_sync(0xffffffffu, mx0, 2));
        mx1 = fmaxf(mx1, __shfl_xor_sync(0xffffffffu, mx1, 1));
        mx1 = fmaxf(mx1, __shfl_xor_sync(0xffffffffu, mx1, 2));

        float mn0 = fmaxf(m2[0], mx0);
        float mn1 = fmaxf(m2[1], mx1);
        float c0 = exp2f(m2[0] - mn0);
        float c1 = exp2f(m2[1] - mn1);
        m2[0] = mn0; m2[1] = mn1;
        ls[0] *= c0; ls[1] *= c1;
        #pragma unroll
        for (int nt = 0; nt < 8; nt++) {
            o[nt][0] *= c0; o[nt][1] *= c0;
            o[nt][2] *= c1; o[nt][3] *= c1;
        }

        // --- P = exp2(s - m), paired-col store (raw fp32; mma truncates) ---
        #pragma unroll
        for (int nt = 0; nt < 4; nt++) {
            float p0 = exp2f(s[nt][0] - mn0);
            float p1 = exp2f(s[nt][1] - mn0);
            float p2 = exp2f(s[nt][2] - mn1);
            float p3 = exp2f(s[nt][3] - mn1);
            ls[0] += p0 + p1;
            ls[1] += p2 + p3;
            Ps[rg    ][nt * 8 + pkA] = p0;
            Ps[rg    ][nt * 8 + pkB] = p1;
            Ps[rg + 8][nt * 8 + pkA] = p2;
            Ps[rg + 8][nt * 8 + pkB] = p3;
        }
        __syncwarp();

        // --- reload P as A-frags via LDS.64 ---
        uint32_t pa[4][4];
        #pragma unroll
        for (int kt = 0; kt < 4; kt++) {
            float2 u0 = *(const float2*)&Ps[rg    ][kt * 8 + 2 * t];
            float2 u1 = *(const float2*)&Ps[rg + 8][kt * 8 + 2 * t];
            pa[kt][0] = __float_as_uint(u0.x);
            pa[kt][1] = __float_as_uint(u1.x);
            pa[kt][2] = __float_as_uint(u0.y);
            pa[kt][3] = __float_as_uint(u1.y);
        }

        // --- O += P @ V ---
        #pragma unroll
        for (int nt = 0; nt < 8; nt++) {
            #pragma unroll
            for (int kt = 0; kt < 4; kt++) {
                uint32_t b0 = __float_as_uint(Vs[stage][kt * 8 + t    ][nt * 8 + g]);
                uint32_t b1 = __float_as_uint(Vs[stage][kt * 8 + t + 4][nt * 8 + g]);
                mma8(o[nt], pa[kt], b0, b1);
            }
        }

        __syncthreads();   // stage fully consumed before next iteration reuses it
    }

    // --- normalize and write out[b, s, h*64 + d] ---
    ls[0] += __shfl_xor_sync(0xffffffffu, ls[0], 1);
    ls[0] += __shfl_xor_sync(0xffffffffu, ls[0], 2);
    ls[1] += __shfl_xor_sync(0xffffffffu, ls[1], 1);
    ls[1] += __shfl_xor_sync(0xffffffffu, ls[1], 2);
    float i0 = 1.f / ls[0];
    float i1 = 1.f / ls[1];

    const int orow = b * SEQ + q0 + warp * 16;
    #pragma unroll
    for (int nt = 0; nt < 8; nt++) {
        int col = h * HD + nt * 8 + 2 * t;
        float2 v0 = make_float2(o[nt][0] * i0, o[nt][1] * i0);
        float2 v1 = make_float2(o[nt][2] * i1, o[nt][3] * i1);
        *(float2*)&out[(size_t)(orow + g    ) * DMODEL + col] = v0;
        *(float2*)&out[(size_t)(orow + g + 8) * DMODEL + col] = v1;
    }
}

// ======================================================================
// launch
// ======================================================================
extern "C" void kernel_launch(void* const* d_in, const int* in_sizes, int n_in,
                              void* d_out, int out_size)
{
    const float* x  = (const float*)d_in[0];
    const float* Wq = (const float*)d_in[1];
    const float* bq = (const float*)d_in[2];
    const float* Wk = (const float*)d_in[3];
    const float* bk = (const float*)d_in[4];
    const float* Wv = (const float*)d_in[5];
    const float* bv = (const float*)d_in[6];
    float* out = (float*)d_out;

    dim3 gg(DMODEL / 128, MTOT / 128, 3);   // (8, 32, 3)
    qkv_gemm<<<gg, 256>>>(x, Wq, Wk, Wv, bq, bk, bv);

    dim3 ga(SEQ / 64, 2 * NH);              // (32, 32)
    attn_kernel<<<ga, 128>>>(out);
}

// round 7
// speedup vs baseline: 1.0456x; 1.0456x over previous
#include <cuda_runtime.h>
#include <cstdint>
#include <math.h>

// Problem constants: B=2, S=2048, D=1024, H=16, hd=64
#define SEQ   2048
#define DMODEL 1024
#define NH    16
#define HD    64
#define MTOT  4096   // B*S

// ---------------- scratch (no cudaMalloc allowed) ----------------
// All three hold tf32-rounded bits (converted in qkv_gemm epilogue).
// g_K additionally stores each 8-dim group pair-permuted:
//   within group: pos = ((d&3)<<1) | ((d&7)>>2)  so (d, d+4) are adjacent.
__device__ float g_Q[MTOT * DMODEL];
__device__ float g_K[MTOT * DMODEL];
__device__ float g_V[MTOT * DMODEL];

// ---------------- helpers ----------------
__device__ __forceinline__ uint32_t f2tf(float x) {
    uint32_t u;
    asm("cvt.rna.tf32.f32 %0, %1;" : "=r"(u) : "f"(x));
    return u;
}

__device__ __forceinline__ void mma8(float* c, const uint32_t* a, uint32_t b0, uint32_t b1) {
    asm volatile(
        "mma.sync.aligned.m16n8k8.row.col.f32.tf32.tf32.f32 "
        "{%0,%1,%2,%3}, {%4,%5,%6,%7}, {%8,%9}, {%0,%1,%2,%3};"
        : "+f"(c[0]), "+f"(c[1]), "+f"(c[2]), "+f"(c[3])
        : "r"(a[0]), "r"(a[1]), "r"(a[2]), "r"(a[3]), "r"(b0), "r"(b1));
}

// ======================================================================
// Kernel 1: QKV projection GEMM (unchanged — verified correct).
// Epilogue writes tf32-rounded values; K is pair-permuted per 8-group.
// ======================================================================
__global__ __launch_bounds__(256) void qkv_gemm(
    const float* __restrict__ x,
    const float* __restrict__ Wq, const float* __restrict__ Wk, const float* __restrict__ Wv,
    const float* __restrict__ bq, const float* __restrict__ bk, const float* __restrict__ bv)
{
    __shared__ float As[128][36];   // frag bank (4g+t)%32, conflict-free
    __shared__ float Bs[32][136];   // frag bank (8t+g)%32, conflict-free

    const float* W; const float* bias; float* outp;
    if (blockIdx.z == 0)      { W = Wq; bias = bq; outp = g_Q; }
    else if (blockIdx.z == 1) { W = Wk; bias = bk; outp = g_K; }
    else                      { W = Wv; bias = bv; outp = g_V; }

    const int tid  = threadIdx.x;
    const int warp = tid >> 5, lane = tid & 31;
    const int g = lane >> 2, t = lane & 3;
    const int wr = warp >> 1;          // 0..3 (m)
    const int wc = warp & 1;           // 0..1 (n)
    const int m0 = blockIdx.y * 128;
    const int n0 = blockIdx.x * 128;

    float acc[2][8][4] = {};

    for (int k0 = 0; k0 < DMODEL; k0 += 32) {
        #pragma unroll
        for (int r = 0; r < 4; r++) {
            int i = tid + 256 * r;           // 0..1023
            int row = i >> 3;
            int c4  = (i & 7) << 2;
            float4 v = *(const float4*)&x[(m0 + row) * DMODEL + k0 + c4];
            As[row][c4 + 0] = __uint_as_float(f2tf(v.x));
            As[row][c4 + 1] = __uint_as_float(f2tf(v.y));
            As[row][c4 + 2] = __uint_as_float(f2tf(v.z));
            As[row][c4 + 3] = __uint_as_float(f2tf(v.w));
        }
        #pragma unroll
        for (int r = 0; r < 4; r++) {
            int i = tid + 256 * r;
            int row = i >> 5;
            int c4  = (i & 31) << 2;
            float4 v = *(const float4*)&W[(k0 + row) * DMODEL + n0 + c4];
            Bs[row][c4 + 0] = __uint_as_float(f2tf(v.x));
            Bs[row][c4 + 1] = __uint_as_float(f2tf(v.y));
            Bs[row][c4 + 2] = __uint_as_float(f2tf(v.z));
            Bs[row][c4 + 3] = __uint_as_float(f2tf(v.w));
        }
        __syncthreads();

        #pragma unroll
        for (int ks = 0; ks < 4; ks++) {
            const int kk = ks * 8;
            uint32_t a[2][4], bb[8][2];
            #pragma unroll
            for (int mt = 0; mt < 2; mt++) {
                int rb = wr * 32 + mt * 16;
                a[mt][0] = __float_as_uint(As[rb + g    ][kk + t    ]);
                a[mt][1] = __float_as_uint(As[rb + g + 8][kk + t    ]);
                a[mt][2] = __float_as_uint(As[rb + g    ][kk + t + 4]);
                a[mt][3] = __float_as_uint(As[rb + g + 8][kk + t + 4]);
            }
            #pragma unroll
            for (int nt = 0; nt < 8; nt++) {
                int cb = wc * 64 + nt * 8;
                bb[nt][0] = __float_as_uint(Bs[kk + t    ][cb + g]);
                bb[nt][1] = __float_as_uint(Bs[kk + t + 4][cb + g]);
            }
            #pragma unroll
            for (int mt = 0; mt < 2; mt++)
                #pragma unroll
                for (int nt = 0; nt < 8; nt++)
                    mma8(acc[mt][nt], a[mt], bb[nt][0], bb[nt][1]);
        }
        __syncthreads();
    }

    // epilogue: + bias, convert to tf32 bits, write.
    const bool isK = (blockIdx.z == 1);
    #pragma unroll
    for (int mt = 0; mt < 2; mt++) {
        int row = m0 + wr * 32 + mt * 16 + g;
        #pragma unroll
        for (int nt = 0; nt < 8; nt++) {
            int col = n0 + wc * 64 + nt * 8 + 2 * t;
            float b0v = bias[col], b1v = bias[col + 1];
            float e00 = __uint_as_float(f2tf(acc[mt][nt][0] + b0v));
            float e01 = __uint_as_float(f2tf(acc[mt][nt][1] + b1v));
            float e10 = __uint_as_float(f2tf(acc[mt][nt][2] + b0v));
            float e11 = __uint_as_float(f2tf(acc[mt][nt][3] + b1v));
            if (isK) {
                // pair-permute within the 8-group: w -> ((w&3)<<1) | (w>>2)
                int wbase = col & ~7;
                int p0 = wbase + (((2 * t)     & 3) << 1) + (t >> 1);
                int p1 = wbase + (((2 * t + 1) & 3) << 1) + (t >> 1);
                outp[(size_t)row       * DMODEL + p0] = e00;
                outp[(size_t)row       * DMODEL + p1] = e01;
                outp[(size_t)(row + 8) * DMODEL + p0] = e10;
                outp[(size_t)(row + 8) * DMODEL + p1] = e11;
            } else {
                *(float2*)&outp[(size_t)row       * DMODEL + col] = make_float2(e00, e01);
                *(float2*)&outp[(size_t)(row + 8) * DMODEL + col] = make_float2(e10, e11);
            }
        }
    }
}

// ======================================================================
// Kernel 2: flash attention v5 — operand reuse.
// grid = (SEQ/128, B*NH), 128 threads (4 warps).
// Each warp owns 32 q-rows (two m16 A-fragments): every K/V b-fragment
// load feeds 2 MMAs -> smem bytes per q-row drop ~42% vs R1.
// No cp.async (regressed in R5); plain LDG->STS.128 fill (R1-proven).
// ======================================================================
#define KVT     32
#define NTILES  (SEQ / KVT)      // 64
#define KS_STRIDE 72
#define PS_STRIDE 40

__global__ __launch_bounds__(128) void attn_kernel(float* __restrict__ out)
{
    __shared__ float Ks[KVT][KS_STRIDE];   // paired-d layout (as stored in g_K)
    __shared__ float Vs[KVT][KS_STRIDE];   // plain [key][d]
    __shared__ float Ps[128][PS_STRIDE];   // paired-col P, 32 rows per warp

    const int tid = threadIdx.x, warp = tid >> 5, lane = tid & 31;
    const int g = lane >> 2, t = lane & 3;
    const int bh = blockIdx.y;
    const int b  = bh >> 4;
    const int h  = bh & 15;
    const int q0 = blockIdx.x * 128;

    const float* Kbase = g_K + (size_t)(b * SEQ) * DMODEL + h * HD;
    const float* Vbase = g_V + (size_t)(b * SEQ) * DMODEL + h * HD;

    // fill roles: thread -> (key row, 16-float chunk)
    const int frow = tid >> 2;              // 0..31
    const int fc   = (tid & 3) * 16;        // 0,16,32,48

    // --- Q fragments: two m16 tiles per warp (rows warp*32 .. +31) ---
    const int qrow = b * SEQ + q0 + warp * 32;
    uint32_t qa[2][8][4];
    #pragma unroll
    for (int m = 0; m < 2; m++) {
        const size_t r0 = (size_t)(qrow + m * 16 + g) * DMODEL + h * HD;
        const size_t r8 = (size_t)(qrow + m * 16 + g + 8) * DMODEL + h * HD;
        #pragma unroll
        for (int kt = 0; kt < 8; kt++) {
            qa[m][kt][0] = __float_as_uint(g_Q[r0 + kt * 8 + t    ]);
            qa[m][kt][1] = __float_as_uint(g_Q[r8 + kt * 8 + t    ]);
            qa[m][kt][2] = __float_as_uint(g_Q[r0 + kt * 8 + t + 4]);
            qa[m][kt][3] = __float_as_uint(g_Q[r8 + kt * 8 + t + 4]);
        }
    }

    float m2[2][2];
    float ls[2][2];
    #pragma unroll
    for (int m = 0; m < 2; m++) { m2[m][0] = m2[m][1] = -INFINITY; ls[m][0] = ls[m][1] = 0.f; }
    float o[2][8][4] = {};

    const float SC = 0.125f * 1.44269504088896f;  // 1/sqrt(64) * log2(e)

    // paired-column P store positions
    const int pkA = (((2 * t)     & 3) << 1) + (t >> 1);   // col 2t
    const int pkB = (((2 * t + 1) & 3) << 1) + (t >> 1);   // col 2t+1

    for (int kv0 = 0; kv0 < SEQ; kv0 += KVT) {
        // --- fill K,V (pure byte copy; data already tf32 + K permuted) ---
        {
            const float* kp = Kbase + (size_t)(kv0 + frow) * DMODEL + fc;
            const float* vp = Vbase + (size_t)(kv0 + frow) * DMODEL + fc;
            float4 k0v = *(const float4*)kp;
            float4 k1v = *(const float4*)(kp + 4);
            float4 k2v = *(const float4*)(kp + 8);
            float4 k3v = *(const float4*)(kp + 12);
            *(float4*)&Ks[frow][fc     ] = k0v;
            *(float4*)&Ks[frow][fc + 4 ] = k1v;
            *(float4*)&Ks[frow][fc + 8 ] = k2v;
            *(float4*)&Ks[frow][fc + 12] = k3v;
            float4 v0v = *(const float4*)vp;
            float4 v1v = *(const float4*)(vp + 4);
            float4 v2v = *(const float4*)(vp + 8);
            float4 v3v = *(const float4*)(vp + 12);
            *(float4*)&Vs[frow][fc     ] = v0v;
            *(float4*)&Vs[frow][fc + 4 ] = v1v;
            *(float4*)&Vs[frow][fc + 8 ] = v2v;
            *(float4*)&Vs[frow][fc + 12] = v3v;
        }
        __syncthreads();

        // --- S = Q @ K^T : each K b-frag (LDS.64) feeds both m halves ---
        float s[2][4][4] = {};
        #pragma unroll
        for (int nt = 0; nt < 4; nt++) {
            #pragma unroll
            for (int kt = 0; kt < 8; kt++) {
                float2 bb = *(const float2*)&Ks[nt * 8 + g][kt * 8 + 2 * t];
                uint32_t b0 = __float_as_uint(bb.x), b1 = __float_as_uint(bb.y);
                mma8(s[0][nt], qa[0][kt], b0, b1);
                mma8(s[1][nt], qa[1][kt], b0, b1);
            }
        }

        // --- softmax (log2 domain) + P store, per m half ---
        #pragma unroll
        for (int m = 0; m < 2; m++) {
            float mx0 = -INFINITY, mx1 = -INFINITY;
            #pragma unroll
            for (int nt = 0; nt < 4; nt++) {
                s[m][nt][0] *= SC; s[m][nt][1] *= SC; s[m][nt][2] *= SC; s[m][nt][3] *= SC;
                mx0 = fmaxf(mx0, fmaxf(s[m][nt][0], s[m][nt][1]));
                mx1 = fmaxf(mx1, fmaxf(s[m][nt][2], s[m][nt][3]));
            }
            mx0 = fmaxf(mx0, __shfl_xor_sync(0xffffffffu, mx0, 1));
            mx0 = fmaxf(mx0, __shfl_xor_sync(0xffffffffu, mx0, 2));
            mx1 = fmaxf(mx1, __shfl_xor_sync(0xffffffffu, mx1, 1));
            mx1 = fmaxf(mx1, __shfl_xor_sync(0xffffffffu, mx1, 2));

            float mn0 = fmaxf(m2[m][0], mx0);
            float mn1 = fmaxf(m2[m][1], mx1);
            float c0 = exp2f(m2[m][0] - mn0);
            float c1 = exp2f(m2[m][1] - mn1);
            m2[m][0] = mn0; m2[m][1] = mn1;
            ls[m][0] *= c0; ls[m][1] *= c1;
            #pragma unroll
            for (int nt = 0; nt < 8; nt++) {
                o[m][nt][0] *= c0; o[m][nt][1] *= c0;
                o[m][nt][2] *= c1; o[m][nt][3] *= c1;
            }

            const int rg = warp * 32 + m * 16 + g;
            #pragma unroll
            for (int nt = 0; nt < 4; nt++) {
                float p0 = exp2f(s[m][nt][0] - mn0);
                float p1 = exp2f(s[m][nt][1] - mn0);
                float p2 = exp2f(s[m][nt][2] - mn1);
                float p3 = exp2f(s[m][nt][3] - mn1);
                ls[m][0] += p0 + p1;
                ls[m][1] += p2 + p3;
                Ps[rg    ][nt * 8 + pkA] = p0;
                Ps[rg    ][nt * 8 + pkB] = p1;
                Ps[rg + 8][nt * 8 + pkA] = p2;
                Ps[rg + 8][nt * 8 + pkB] = p3;
            }
        }
        __syncwarp();

        // --- reload P as A-frags (LDS.64) for both halves ---
        uint32_t pa[2][4][4];
        #pragma unroll
        for (int m = 0; m < 2; m++) {
            const int rg = warp * 32 + m * 16 + g;
            #pragma unroll
            for (int kt = 0; kt < 4; kt++) {
                float2 u0 = *(const float2*)&Ps[rg    ][kt * 8 + 2 * t];
                float2 u1 = *(const float2*)&Ps[rg + 8][kt * 8 + 2 * t];
                pa[m][kt][0] = __float_as_uint(u0.x);
                pa[m][kt][1] = __float_as_uint(u1.x);
                pa[m][kt][2] = __float_as_uint(u0.y);
                pa[m][kt][3] = __float_as_uint(u1.y);
            }
        }

        // --- O += P @ V : each V b-frag feeds both m halves ---
        #pragma unroll
        for (int nt = 0; nt < 8; nt++) {
            #pragma unroll
            for (int kt = 0; kt < 4; kt++) {
                uint32_t b0 = __float_as_uint(Vs[kt * 8 + t    ][nt * 8 + g]);
                uint32_t b1 = __float_as_uint(Vs[kt * 8 + t + 4][nt * 8 + g]);
                mma8(o[0][nt], pa[0][kt], b0, b1);
                mma8(o[1][nt], pa[1][kt], b0, b1);
            }
        }

        __syncthreads();   // tile fully consumed before refill
    }

    // --- normalize and write out[b, s, h*64 + d] ---
    #pragma unroll
    for (int m = 0; m < 2; m++) {
        float l0 = ls[m][0], l1 = ls[m][1];
        l0 += __shfl_xor_sync(0xffffffffu, l0, 1);
        l0 += __shfl_xor_sync(0xffffffffu, l0, 2);
        l1 += __shfl_xor_sync(0xffffffffu, l1, 1);
        l1 += __shfl_xor_sync(0xffffffffu, l1, 2);
        float i0 = 1.f / l0;
        float i1 = 1.f / l1;

        const int orow = b * SEQ + q0 + warp * 32 + m * 16;
        #pragma unroll
        for (int nt = 0; nt < 8; nt++) {
            int col = h * HD + nt * 8 + 2 * t;
            float2 v0 = make_float2(o[m][nt][0] * i0, o[m][nt][1] * i0);
            float2 v1 = make_float2(o[m][nt][2] * i1, o[m][nt][3] * i1);
            *(float2*)&out[(size_t)(orow + g    ) * DMODEL + col] = v0;
            *(float2*)&out[(size_t)(orow + g + 8) * DMODEL + col] = v1;
        }
    }
}

// ======================================================================
// launch
// ======================================================================
extern "C" void kernel_launch(void* const* d_in, const int* in_sizes, int n_in,
                              void* d_out, int out_size)
{
    const float* x  = (const float*)d_in[0];
    const float* Wq = (const float*)d_in[1];
    const float* bq = (const float*)d_in[2];
    const float* Wk = (const float*)d_in[3];
    const float* bk = (const float*)d_in[4];
    const float* Wv = (const float*)d_in[5];
    const float* bv = (const float*)d_in[6];
    float* out = (float*)d_out;

    dim3 gg(DMODEL / 128, MTOT / 128, 3);   // (8, 32, 3)
    qkv_gemm<<<gg, 256>>>(x, Wq, Wk, Wv, bq, bk, bv);

    dim3 ga(SEQ / 128, 2 * NH);             // (16, 32)
    attn_kernel<<<ga, 128>>>(out);
}